// round 2
// baseline (speedup 1.0000x reference)
#include <cuda_runtime.h>
#include <cstdint>

#define MAXN 50000
#define MAXE 800000
#define HID 128

// ---- static scratch (no allocations allowed) ----
__device__ float g_buf0[(size_t)MAXN * HID];
__device__ float g_buf1[(size_t)MAXN * HID];
__device__ float g_buf2[(size_t)MAXN * HID];
__device__ float g_dinv[MAXN];
__device__ float g_sum[HID];
__device__ float g_sumsq[HID];
__device__ float g_scale[HID];
__device__ float g_shift[HID];
__device__ int   g_cnt[MAXN];
__device__ int   g_rowoff[MAXN + 1];
__device__ int   g_cursor[MAXN];
__device__ int   g_csr_src[MAXE];

// ---------------------------------------------------------------------------
__global__ void zero_aux(int* __restrict__ cnt, float* __restrict__ sum,
                         float* __restrict__ sumsq, int n)
{
    int i = blockIdx.x * blockDim.x + threadIdx.x;
    if (i < n) cnt[i] = 0;
    if (i < HID) { sum[i] = 0.0f; sumsq[i] = 0.0f; }
}

__global__ void hist_dst(const int* __restrict__ dst, int* __restrict__ cnt, int E)
{
    int i = blockIdx.x * blockDim.x + threadIdx.x;
    if (i < E) atomicAdd(&cnt[dst[i]], 1);
}

// Single-block exclusive scan over cnt[0..n). Also emits cursor copy and dinv.
__global__ __launch_bounds__(1024)
void scan_offsets(const int* __restrict__ cnt, int* __restrict__ rowoff,
                  int* __restrict__ cursor, float* __restrict__ dinv, int n)
{
    const int T = 1024;
    int t = threadIdx.x;
    int chunk = (n + T - 1) / T;
    int beg = t * chunk;
    int end = min(beg + chunk, n);

    int s = 0;
    for (int i = beg; i < end; i++) s += cnt[i];

    __shared__ int part[T];
    part[t] = s;
    __syncthreads();
    for (int o = 1; o < T; o <<= 1) {
        int add = (t >= o) ? part[t - o] : 0;
        __syncthreads();
        part[t] += add;
        __syncthreads();
    }
    int run = part[t] - s;   // exclusive prefix of this chunk
    for (int i = beg; i < end; i++) {
        rowoff[i] = run;
        cursor[i] = run;
        dinv[i]   = rsqrtf((float)cnt[i] + 1.0f);
        run += cnt[i];
    }
    if (t == T - 1) rowoff[n] = run;
}

__global__ void fill_csr(const int* __restrict__ src, const int* __restrict__ dst,
                         int* __restrict__ cursor, int* __restrict__ csr_src, int E)
{
    int e = blockIdx.x * blockDim.x + threadIdx.x;
    if (e < E) {
        int d = dst[e];
        int pos = atomicAdd(&cursor[d], 1);
        csr_src[pos] = src[e];
    }
}

// ---------------------------------------------------------------------------
// C[M,128] = A[M,128] @ W[128,128], fp32, double-buffered smem, 1 barrier/iter.
__global__ __launch_bounds__(256)
void sgemm128(const float* __restrict__ A, const float* __restrict__ W,
              float* __restrict__ C, int M)
{
    __shared__ __align__(16) float As[2][8][128];
    __shared__ __align__(16) float Bs[2][8][128];

    const int blockRow = blockIdx.x * 128;
    const int tid = threadIdx.x;
    const int tm = tid >> 4;
    const int tn = tid & 15;

    const int arow  = tid >> 1;
    const int acol4 = (tid & 1) * 4;
    const int brow  = tid >> 5;
    const int bcol4 = (tid & 31) * 4;

    float acc[8][8];
#pragma unroll
    for (int i = 0; i < 8; i++)
#pragma unroll
        for (int j = 0; j < 8; j++) acc[i][j] = 0.0f;

    const int gr_a = blockRow + arow;
    const bool a_ok = (gr_a < M);
    const float4* Ap = (const float4*)(A + (size_t)gr_a * HID + acol4);
    const float4* Wp = (const float4*)(W + (size_t)brow * HID + bcol4);

    // prologue: stage k-tile 0
    {
        float4 av = a_ok ? Ap[0] : make_float4(0.f, 0.f, 0.f, 0.f);
        float4 bv = Wp[0];
        As[0][acol4 + 0][arow] = av.x;
        As[0][acol4 + 1][arow] = av.y;
        As[0][acol4 + 2][arow] = av.z;
        As[0][acol4 + 3][arow] = av.w;
        *(float4*)(&Bs[0][brow][bcol4]) = bv;
    }
    __syncthreads();

#pragma unroll
    for (int it = 0; it < 16; it++) {
        const int cur = it & 1;
        const int nxt = cur ^ 1;
        float4 av_n, bv_n;
        if (it < 15) {
            av_n = a_ok ? Ap[2 * (it + 1)] : make_float4(0.f, 0.f, 0.f, 0.f);
            bv_n = Wp[256 * (it + 1)];
        }

#pragma unroll
        for (int kk = 0; kk < 8; kk++) {
            float ra[8], rb[8];
#pragma unroll
            for (int i = 0; i < 8; i++) ra[i] = As[cur][kk][tm * 8 + i];
#pragma unroll
            for (int j = 0; j < 8; j++) rb[j] = Bs[cur][kk][tn * 8 + j];
#pragma unroll
            for (int i = 0; i < 8; i++)
#pragma unroll
                for (int j = 0; j < 8; j++) acc[i][j] += ra[i] * rb[j];
        }

        if (it < 15) {
            As[nxt][acol4 + 0][arow] = av_n.x;
            As[nxt][acol4 + 1][arow] = av_n.y;
            As[nxt][acol4 + 2][arow] = av_n.z;
            As[nxt][acol4 + 3][arow] = av_n.w;
            *(float4*)(&Bs[nxt][brow][bcol4]) = bv_n;
        }
        __syncthreads();
    }

#pragma unroll
    for (int i = 0; i < 8; i++) {
        int gr = blockRow + tm * 8 + i;
        if (gr < M) {
            float4 v0 = make_float4(acc[i][0], acc[i][1], acc[i][2], acc[i][3]);
            float4 v1 = make_float4(acc[i][4], acc[i][5], acc[i][6], acc[i][7]);
            *(float4*)(C + (size_t)gr * HID + tn * 8)     = v0;
            *(float4*)(C + (size_t)gr * HID + tn * 8 + 4) = v1;
        }
    }
}

// ---------------------------------------------------------------------------
// agg[n,:] = sum_{e: dst=n} h[src_e,:]*dinv[src]*dinv[n]  + h[n,:]*dinv[n]^2 + b
// one warp per dst node; CSR gather, no atomics.
__global__ __launch_bounds__(256)
void gcn_aggregate(const float* __restrict__ h, float* __restrict__ agg,
                   const int* __restrict__ rowoff, const int* __restrict__ csr_src,
                   const float* __restrict__ dinv, const float* __restrict__ bias,
                   int Nn)
{
    int lane = threadIdx.x & 31;
    int n = (blockIdx.x * blockDim.x + threadIdx.x) >> 5;
    if (n >= Nn) return;
    int c4 = lane * 4;

    float din = dinv[n];
    float w = din * din;
    float4 v  = *(const float4*)(h + (size_t)n * HID + c4);
    float4 bb = *(const float4*)(bias + c4);
    float4 acc;
    acc.x = v.x * w + bb.x;
    acc.y = v.y * w + bb.y;
    acc.z = v.z * w + bb.z;
    acc.w = v.w * w + bb.w;

    int beg = rowoff[n], end = rowoff[n + 1];
    int j = beg;
    for (; j + 2 <= end; j += 2) {
        int s0 = __ldg(&csr_src[j]);
        int s1 = __ldg(&csr_src[j + 1]);
        float n0 = dinv[s0] * din;
        float n1 = dinv[s1] * din;
        float4 v0 = *(const float4*)(h + (size_t)s0 * HID + c4);
        float4 v1 = *(const float4*)(h + (size_t)s1 * HID + c4);
        acc.x += v0.x * n0; acc.y += v0.y * n0; acc.z += v0.z * n0; acc.w += v0.w * n0;
        acc.x += v1.x * n1; acc.y += v1.y * n1; acc.z += v1.z * n1; acc.w += v1.w * n1;
    }
    if (j < end) {
        int s0 = __ldg(&csr_src[j]);
        float n0 = dinv[s0] * din;
        float4 v0 = *(const float4*)(h + (size_t)s0 * HID + c4);
        acc.x += v0.x * n0; acc.y += v0.y * n0; acc.z += v0.z * n0; acc.w += v0.w * n0;
    }
    *(float4*)(agg + (size_t)n * HID + c4) = acc;
}

// ---------------------------------------------------------------------------
__global__ __launch_bounds__(256)
void bn_stats(const float* __restrict__ z, float* __restrict__ sum,
              float* __restrict__ sumsq, int Nn)
{
    int c    = threadIdx.x & 127;
    int half = threadIdx.x >> 7;
    float s = 0.f, q = 0.f;
    for (int r = blockIdx.x * 2 + half; r < Nn; r += gridDim.x * 2) {
        float v = z[(size_t)r * HID + c];
        s += v;
        q += v * v;
    }
    __shared__ float sh[256];
    sh[threadIdx.x] = s;
    __syncthreads();
    if (half == 0) atomicAdd(&sum[c], sh[c] + sh[c + 128]);
    __syncthreads();
    sh[threadIdx.x] = q;
    __syncthreads();
    if (half == 0) atomicAdd(&sumsq[c], sh[c] + sh[c + 128]);
}

__global__ void bn_final(const float* __restrict__ sum, const float* __restrict__ sumsq,
                         const float* __restrict__ gamma, const float* __restrict__ beta,
                         float* __restrict__ scale, float* __restrict__ shift, int Nn)
{
    int i = threadIdx.x;
    if (i < HID) {
        float invN = 1.0f / (float)Nn;
        float mean = sum[i] * invN;
        float var  = sumsq[i] * invN - mean * mean;
        float sc   = gamma[i] * rsqrtf(var + 1e-5f);
        scale[i] = sc;
        shift[i] = beta[i] - mean * sc;
    }
}

__global__ void bn_apply(float* __restrict__ z, const float* __restrict__ scale,
                         const float* __restrict__ shift, int Nn)
{
    int idx = blockIdx.x * blockDim.x + threadIdx.x;
    int total = Nn * (HID / 4);
    if (idx >= total) return;
    int c4 = (idx & 31) * 4;
    float4 v  = *(float4*)(z + (size_t)idx * 4);
    float4 sc = *(const float4*)(scale + c4);
    float4 sh = *(const float4*)(shift + c4);
    v.x = fmaxf(v.x * sc.x + sh.x, 0.f);
    v.y = fmaxf(v.y * sc.y + sh.y, 0.f);
    v.z = fmaxf(v.z * sc.z + sh.z, 0.f);
    v.w = fmaxf(v.w * sc.w + sh.w, 0.f);
    *(float4*)(z + (size_t)idx * 4) = v;
}

// ---------------------------------------------------------------------------
// out[e] = relu(A[src] + B[dst] + edge_attr[e]@We + bm1) . Wm2 + bm2
__global__ __launch_bounds__(256)
void edge_mlp(const float* __restrict__ A, const float* __restrict__ B,
              const int* __restrict__ src, const int* __restrict__ dst,
              const float* __restrict__ ea, const float* __restrict__ We,  // [16,128]
              const float* __restrict__ bm1, const float* __restrict__ Wm2,
              const float* __restrict__ bm2, float* __restrict__ out, int E)
{
    __shared__ __align__(16) float sWe[16][128];
    __shared__ __align__(16) float sb[128];
    __shared__ __align__(16) float sw2[128];
    for (int i = threadIdx.x; i < 16 * 128; i += blockDim.x)
        sWe[i >> 7][i & 127] = We[i];
    for (int i = threadIdx.x; i < 128; i += blockDim.x) {
        sb[i]  = bm1[i];
        sw2[i] = Wm2[i];
    }
    __syncthreads();
    const float bm2v = bm2[0];

    int lane = threadIdx.x & 31;
    int warp = (blockIdx.x * blockDim.x + threadIdx.x) >> 5;
    int nw   = (gridDim.x * blockDim.x) >> 5;
    int c4   = lane * 4;

    float4 bias = *(const float4*)(&sb[c4]);
    float4 w2   = *(const float4*)(&sw2[c4]);

    for (int e = warp; e < E; e += nw) {
        int s = src[e], d = dst[e];
        float4 a = *(const float4*)(A + (size_t)s * HID + c4);
        float4 b = *(const float4*)(B + (size_t)d * HID + c4);
        float4 acc;
        acc.x = a.x + b.x + bias.x;
        acc.y = a.y + b.y + bias.y;
        acc.z = a.z + b.z + bias.z;
        acc.w = a.w + b.w + bias.w;

        float eav = (lane < 16) ? ea[(size_t)e * 16 + lane] : 0.0f;
#pragma unroll
        for (int k = 0; k < 16; k++) {
            float ek = __shfl_sync(0xffffffff, eav, k);
            float4 w = *(const float4*)(&sWe[k][c4]);
            acc.x += ek * w.x;
            acc.y += ek * w.y;
            acc.z += ek * w.z;
            acc.w += ek * w.w;
        }
        acc.x = fmaxf(acc.x, 0.f);
        acc.y = fmaxf(acc.y, 0.f);
        acc.z = fmaxf(acc.z, 0.f);
        acc.w = fmaxf(acc.w, 0.f);

        float p = acc.x * w2.x + acc.y * w2.y + acc.z * w2.z + acc.w * w2.w;
#pragma unroll
        for (int o = 16; o; o >>= 1) p += __shfl_xor_sync(0xffffffff, p, o);
        if (lane == 0) out[e] = p + bm2v;
    }
}

// ---------------------------------------------------------------------------
extern "C" void kernel_launch(void* const* d_in, const int* in_sizes, int n_in,
                              void* d_out, int out_size)
{
    const float* x     = (const float*)d_in[0];
    const int*   ei    = (const int*)  d_in[1];
    const float* ea    = (const float*)d_in[2];
    const float* W1    = (const float*)d_in[3];
    const float* b1    = (const float*)d_in[4];
    const float* gamma = (const float*)d_in[5];
    const float* beta  = (const float*)d_in[6];
    const float* W2    = (const float*)d_in[7];
    const float* b2    = (const float*)d_in[8];
    const float* Wm1   = (const float*)d_in[9];
    const float* bm1   = (const float*)d_in[10];
    const float* Wm2   = (const float*)d_in[11];
    const float* bm2   = (const float*)d_in[12];
    float* out = (float*)d_out;

    const int Nn = in_sizes[0] / HID;
    const int E  = in_sizes[1] / 2;
    const int* src = ei;
    const int* dst = ei + E;

    float *buf0, *buf1, *buf2, *dinv, *sum, *sumsq, *scale, *shift;
    int *cnt, *rowoff, *cursor, *csr_src;
    cudaGetSymbolAddress((void**)&buf0,    g_buf0);
    cudaGetSymbolAddress((void**)&buf1,    g_buf1);
    cudaGetSymbolAddress((void**)&buf2,    g_buf2);
    cudaGetSymbolAddress((void**)&dinv,    g_dinv);
    cudaGetSymbolAddress((void**)&sum,     g_sum);
    cudaGetSymbolAddress((void**)&sumsq,   g_sumsq);
    cudaGetSymbolAddress((void**)&scale,   g_scale);
    cudaGetSymbolAddress((void**)&shift,   g_shift);
    cudaGetSymbolAddress((void**)&cnt,     g_cnt);
    cudaGetSymbolAddress((void**)&rowoff,  g_rowoff);
    cudaGetSymbolAddress((void**)&cursor,  g_cursor);
    cudaGetSymbolAddress((void**)&csr_src, g_csr_src);

    const int gN    = (Nn + 255) / 256;
    const int gE    = (E + 255) / 256;
    const int gElem = (Nn * (HID / 4) + 255) / 256;
    const int gGemm = (Nn + 127) / 128;
    const int gAgg  = (Nn * 32 + 255) / 256;

    // CSR build (by dst) + degrees
    zero_aux<<<gN, 256>>>(cnt, sum, sumsq, Nn);
    hist_dst<<<gE, 256>>>(dst, cnt, E);
    scan_offsets<<<1, 1024>>>(cnt, rowoff, cursor, dinv, Nn);
    fill_csr<<<gE, 256>>>(src, dst, cursor, csr_src, E);

    // conv1
    sgemm128<<<gGemm, 256>>>(x, W1, buf0, Nn);
    gcn_aggregate<<<gAgg, 256>>>(buf0, buf1, rowoff, csr_src, dinv, b1, Nn);

    // batchnorm + relu (in place on buf1)
    bn_stats<<<512, 256>>>(buf1, sum, sumsq, Nn);
    bn_final<<<1, 128>>>(sum, sumsq, gamma, beta, scale, shift, Nn);
    bn_apply<<<gElem, 256>>>(buf1, scale, shift, Nn);

    // conv2
    sgemm128<<<gGemm, 256>>>(buf1, W2, buf2, Nn);
    gcn_aggregate<<<gAgg, 256>>>(buf2, buf0, rowoff, csr_src, dinv, b2, Nn);

    // per-node projections of edge-MLP
    sgemm128<<<gGemm, 256>>>(buf0, Wm1,             buf1, Nn);
    sgemm128<<<gGemm, 256>>>(buf0, Wm1 + 128 * HID, buf2, Nn);

    // fused edge head
    edge_mlp<<<2048, 256>>>(buf1, buf2, src, dst, ea, Wm1 + 256 * HID,
                            bm1, Wm2, bm2, out, E);
}

// round 3
// speedup vs baseline: 1.2204x; 1.2204x over previous
#include <cuda_runtime.h>
#include <cstdint>

#define MAXN 50000
#define MAXE 800000
#define HID 128
#define FULLMASK 0xffffffffu

// ---- static scratch (no allocations allowed) ----
__device__ float g_buf0[(size_t)MAXN * HID];
__device__ float g_buf1[(size_t)MAXN * HID];
__device__ float g_buf2[(size_t)MAXN * HID];
__device__ float g_dinv[MAXN];
__device__ float g_sum[HID];
__device__ float g_sumsq[HID];
__device__ float g_scale[HID];
__device__ float g_shift[HID];
__device__ int   g_cnt[MAXN];
__device__ int   g_rowoff[MAXN + 1];
__device__ int   g_cursor[MAXN];
__device__ int   g_csr_src[MAXE];

// ---------------------------------------------------------------------------
__global__ void zero_aux(int* __restrict__ cnt, float* __restrict__ sum,
                         float* __restrict__ sumsq, int n)
{
    int i = blockIdx.x * blockDim.x + threadIdx.x;
    if (i < n) cnt[i] = 0;
    if (i < HID) { sum[i] = 0.0f; sumsq[i] = 0.0f; }
}

__global__ void hist_dst(const int* __restrict__ dst, int* __restrict__ cnt, int E)
{
    int i = blockIdx.x * blockDim.x + threadIdx.x;
    if (i < E) atomicAdd(&cnt[dst[i]], 1);
}

// Single-block exclusive scan over cnt[0..n). Emits rowoff, cursor, dinv.
__global__ __launch_bounds__(1024)
void scan_offsets(const int* __restrict__ cnt, int* __restrict__ rowoff,
                  int* __restrict__ cursor, float* __restrict__ dinv, int n)
{
    const int T = 1024;
    int t = threadIdx.x;
    int chunk = (n + T - 1) / T;
    int beg = t * chunk;
    int end = min(beg + chunk, n);

    int s = 0;
    for (int i = beg; i < end; i++) s += cnt[i];

    __shared__ int part[T];
    part[t] = s;
    __syncthreads();
    for (int o = 1; o < T; o <<= 1) {
        int add = (t >= o) ? part[t - o] : 0;
        __syncthreads();
        part[t] += add;
        __syncthreads();
    }
    int run = part[t] - s;
    for (int i = beg; i < end; i++) {
        rowoff[i] = run;
        cursor[i] = run;
        dinv[i]   = rsqrtf((float)cnt[i] + 1.0f);
        run += cnt[i];
    }
    if (t == T - 1) rowoff[n] = run;
}

__global__ void fill_csr(const int* __restrict__ src, const int* __restrict__ dst,
                         int* __restrict__ cursor, int* __restrict__ csr_src, int E)
{
    int e = blockIdx.x * blockDim.x + threadIdx.x;
    if (e < E) {
        int d = dst[e];
        int pos = atomicAdd(&cursor[d], 1);
        csr_src[pos] = src[e];
    }
}

// ---------------------------------------------------------------------------
// tf32 tensor-core GEMM with 3xTF32 error compensation.
// C[M,128] = f(A)[M,128] @ W[128,128]; f = optional scale/shift+relu per column.
// 256 threads = 8 warps (4 along M x 2 along N). Warp tile 32x64, mma m16n8k8.
#define SMS 136   // smem row stride (floats): conflict-free for frag loads

__device__ __forceinline__ uint32_t f2tf32(float x)
{
    uint32_t r;
    asm("cvt.rna.tf32.f32 %0, %1;" : "=r"(r) : "f"(x));
    return r;
}

__device__ __forceinline__ void mma_tf32(float c[4], const uint32_t a[4],
                                         uint32_t b0, uint32_t b1)
{
    asm volatile(
        "mma.sync.aligned.m16n8k8.row.col.f32.tf32.tf32.f32 "
        "{%0,%1,%2,%3},{%4,%5,%6,%7},{%8,%9},{%0,%1,%2,%3};"
        : "+f"(c[0]), "+f"(c[1]), "+f"(c[2]), "+f"(c[3])
        : "r"(a[0]), "r"(a[1]), "r"(a[2]), "r"(a[3]), "r"(b0), "r"(b1));
}

__global__ __launch_bounds__(256)
void gemm_tf32(const float* __restrict__ A, const float* __restrict__ W,
               float* __restrict__ C, int M,
               const float* __restrict__ pre_scale,   // may be null
               const float* __restrict__ pre_shift)
{
    extern __shared__ float smem[];
    float* As = smem;              // [128][SMS]
    float* Ws = smem + 128 * SMS;  // [128][SMS]

    const int tid = threadIdx.x;
    const int blockRow = blockIdx.x * 128;
    const bool do_pre = (pre_scale != nullptr);

    // stage A (with optional bn+relu) and W
#pragma unroll
    for (int t = 0; t < 16; t++) {
        int idx = tid + t * 256;            // 0..4095
        int row = idx >> 5;
        int c4  = (idx & 31) * 4;
        int gr  = blockRow + row;
        float4 av = (gr < M) ? *(const float4*)(A + (size_t)gr * HID + c4)
                             : make_float4(0.f, 0.f, 0.f, 0.f);
        if (do_pre) {
            float4 sc = *(const float4*)(pre_scale + c4);
            float4 sh = *(const float4*)(pre_shift + c4);
            av.x = fmaxf(av.x * sc.x + sh.x, 0.f);
            av.y = fmaxf(av.y * sc.y + sh.y, 0.f);
            av.z = fmaxf(av.z * sc.z + sh.z, 0.f);
            av.w = fmaxf(av.w * sc.w + sh.w, 0.f);
        }
        *(float4*)(As + row * SMS + c4) = av;
        *(float4*)(Ws + row * SMS + c4) = *(const float4*)(W + (size_t)row * HID + c4);
    }
    __syncthreads();

    const int lane = tid & 31;
    const int warp = tid >> 5;
    const int g    = lane >> 2;
    const int tig  = lane & 3;
    const int wm   = (warp >> 1) * 32;   // 0,32,64,96
    const int wn   = (warp & 1) * 64;    // 0,64

    float c[2][8][4];
#pragma unroll
    for (int mt = 0; mt < 2; mt++)
#pragma unroll
        for (int nt = 0; nt < 8; nt++)
#pragma unroll
            for (int i = 0; i < 4; i++) c[mt][nt][i] = 0.f;

#pragma unroll
    for (int kt = 0; kt < 16; kt++) {
        const int k0 = kt * 8;
        uint32_t ahi[2][4], alo[2][4];
#pragma unroll
        for (int mt = 0; mt < 2; mt++) {
            int rb = wm + mt * 16;
            float a0 = As[(rb + g)     * SMS + k0 + tig];
            float a1 = As[(rb + g + 8) * SMS + k0 + tig];
            float a2 = As[(rb + g)     * SMS + k0 + tig + 4];
            float a3 = As[(rb + g + 8) * SMS + k0 + tig + 4];
            ahi[mt][0] = f2tf32(a0); alo[mt][0] = f2tf32(a0 - __uint_as_float(ahi[mt][0]));
            ahi[mt][1] = f2tf32(a1); alo[mt][1] = f2tf32(a1 - __uint_as_float(ahi[mt][1]));
            ahi[mt][2] = f2tf32(a2); alo[mt][2] = f2tf32(a2 - __uint_as_float(ahi[mt][2]));
            ahi[mt][3] = f2tf32(a3); alo[mt][3] = f2tf32(a3 - __uint_as_float(ahi[mt][3]));
        }
#pragma unroll
        for (int nt = 0; nt < 8; nt++) {
            int col = wn + nt * 8 + g;
            float b0 = Ws[(k0 + tig)     * SMS + col];
            float b1 = Ws[(k0 + tig + 4) * SMS + col];
            uint32_t bh0 = f2tf32(b0), bh1 = f2tf32(b1);
            uint32_t bl0 = f2tf32(b0 - __uint_as_float(bh0));
            uint32_t bl1 = f2tf32(b1 - __uint_as_float(bh1));
#pragma unroll
            for (int mt = 0; mt < 2; mt++) {
                mma_tf32(c[mt][nt], ahi[mt], bh0, bh1);
                mma_tf32(c[mt][nt], ahi[mt], bl0, bl1);
                mma_tf32(c[mt][nt], alo[mt], bh0, bh1);
            }
        }
    }

    // epilogue
#pragma unroll
    for (int mt = 0; mt < 2; mt++) {
#pragma unroll
        for (int nt = 0; nt < 8; nt++) {
            int row0 = blockRow + wm + mt * 16 + g;
            int col0 = wn + nt * 8 + 2 * tig;
            if (row0 < M)
                *(float2*)(C + (size_t)row0 * HID + col0) = make_float2(c[mt][nt][0], c[mt][nt][1]);
            int row1 = row0 + 8;
            if (row1 < M)
                *(float2*)(C + (size_t)row1 * HID + col0) = make_float2(c[mt][nt][2], c[mt][nt][3]);
        }
    }
}

// ---------------------------------------------------------------------------
// agg[n,:] = sum_{e: dst=n} h[src_e,:]*dinv[src]*dinv[n] + h[n,:]*dinv[n]^2 + b
// one warp per dst node; batch-loads 32 (index, weight) pairs, then gathers.
__global__ __launch_bounds__(256)
void gcn_aggregate(const float* __restrict__ h, float* __restrict__ agg,
                   const int* __restrict__ rowoff, const int* __restrict__ csr_src,
                   const float* __restrict__ dinv, const float* __restrict__ bias,
                   int Nn)
{
    int lane = threadIdx.x & 31;
    int n = (blockIdx.x * blockDim.x + threadIdx.x) >> 5;
    if (n >= Nn) return;
    int c4 = lane * 4;

    float din = dinv[n];
    float w = din * din;
    float4 v  = *(const float4*)(h + (size_t)n * HID + c4);
    float4 bb = *(const float4*)(bias + c4);
    float4 acc;
    acc.x = v.x * w + bb.x;
    acc.y = v.y * w + bb.y;
    acc.z = v.z * w + bb.z;
    acc.w = v.w * w + bb.w;

    int beg = rowoff[n], end = rowoff[n + 1];
    for (int base = beg; base < end; base += 32) {
        int m = end - base;
        int s = 0;
        float ww = 0.f;
        if (lane < m) {
            s = __ldg(&csr_src[base + lane]);
            ww = dinv[s] * din;
        }
        int iters = min(m, 32);
#pragma unroll 4
        for (int j = 0; j < iters; j++) {
            int   sj = __shfl_sync(FULLMASK, s,  j);
            float wj = __shfl_sync(FULLMASK, ww, j);
            float4 hv = *(const float4*)(h + (size_t)sj * HID + c4);
            acc.x += hv.x * wj;
            acc.y += hv.y * wj;
            acc.z += hv.z * wj;
            acc.w += hv.w * wj;
        }
    }
    *(float4*)(agg + (size_t)n * HID + c4) = acc;
}

// ---------------------------------------------------------------------------
__global__ __launch_bounds__(256)
void bn_stats(const float* __restrict__ z, float* __restrict__ sum,
              float* __restrict__ sumsq, int Nn)
{
    int c    = threadIdx.x & 127;
    int half = threadIdx.x >> 7;
    float s = 0.f, q = 0.f;
    for (int r = blockIdx.x * 2 + half; r < Nn; r += gridDim.x * 2) {
        float v = z[(size_t)r * HID + c];
        s += v;
        q += v * v;
    }
    __shared__ float sh[256];
    sh[threadIdx.x] = s;
    __syncthreads();
    if (half == 0) atomicAdd(&sum[c], sh[c] + sh[c + 128]);
    __syncthreads();
    sh[threadIdx.x] = q;
    __syncthreads();
    if (half == 0) atomicAdd(&sumsq[c], sh[c] + sh[c + 128]);
}

__global__ void bn_final(const float* __restrict__ sum, const float* __restrict__ sumsq,
                         const float* __restrict__ gamma, const float* __restrict__ beta,
                         float* __restrict__ scale, float* __restrict__ shift, int Nn)
{
    int i = threadIdx.x;
    if (i < HID) {
        float invN = 1.0f / (float)Nn;
        float mean = sum[i] * invN;
        float var  = sumsq[i] * invN - mean * mean;
        float sc   = gamma[i] * rsqrtf(var + 1e-5f);
        scale[i] = sc;
        shift[i] = beta[i] - mean * sc;
    }
}

// ---------------------------------------------------------------------------
// out[e] = relu(A[src] + B[dst] + edge_attr[e]@We + bm1) . Wm2 + bm2
// One warp per edge; We kept in registers (16 x float4 per lane), ea via
// uniform broadcast loads -> zero shared-memory traffic in the hot loop.
__global__ __launch_bounds__(256)
void edge_mlp(const float* __restrict__ A, const float* __restrict__ B,
              const int* __restrict__ src, const int* __restrict__ dst,
              const float* __restrict__ ea, const float* __restrict__ We,  // [16,128]
              const float* __restrict__ bm1, const float* __restrict__ Wm2,
              const float* __restrict__ bm2, float* __restrict__ out, int E)
{
    int lane = threadIdx.x & 31;
    int warp = (blockIdx.x * blockDim.x + threadIdx.x) >> 5;
    int nw   = (gridDim.x * blockDim.x) >> 5;
    int c4   = lane * 4;

    float4 wreg[16];
#pragma unroll
    for (int k = 0; k < 16; k++)
        wreg[k] = *(const float4*)(We + (size_t)k * HID + c4);
    float4 bias = *(const float4*)(bm1 + c4);
    float4 w2   = *(const float4*)(Wm2 + c4);
    const float bm2v = __ldg(bm2);

    for (int e = warp; e < E; e += nw) {
        int s = __ldg(&src[e]);
        int d = __ldg(&dst[e]);
        float4 a = *(const float4*)(A + (size_t)s * HID + c4);
        float4 b = *(const float4*)(B + (size_t)d * HID + c4);
        float4 acc;
        acc.x = a.x + b.x + bias.x;
        acc.y = a.y + b.y + bias.y;
        acc.z = a.z + b.z + bias.z;
        acc.w = a.w + b.w + bias.w;

        const float4* eap = (const float4*)(ea + (size_t)e * 16);
#pragma unroll
        for (int gq = 0; gq < 4; gq++) {
            float4 e4 = __ldg(&eap[gq]);   // uniform across warp -> broadcast
            float4 w;
            w = wreg[gq * 4 + 0];
            acc.x += e4.x * w.x; acc.y += e4.x * w.y; acc.z += e4.x * w.z; acc.w += e4.x * w.w;
            w = wreg[gq * 4 + 1];
            acc.x += e4.y * w.x; acc.y += e4.y * w.y; acc.z += e4.y * w.z; acc.w += e4.y * w.w;
            w = wreg[gq * 4 + 2];
            acc.x += e4.z * w.x; acc.y += e4.z * w.y; acc.z += e4.z * w.z; acc.w += e4.z * w.w;
            w = wreg[gq * 4 + 3];
            acc.x += e4.w * w.x; acc.y += e4.w * w.y; acc.z += e4.w * w.z; acc.w += e4.w * w.w;
        }
        acc.x = fmaxf(acc.x, 0.f);
        acc.y = fmaxf(acc.y, 0.f);
        acc.z = fmaxf(acc.z, 0.f);
        acc.w = fmaxf(acc.w, 0.f);

        float p = acc.x * w2.x + acc.y * w2.y + acc.z * w2.z + acc.w * w2.w;
#pragma unroll
        for (int o = 16; o; o >>= 1) p += __shfl_xor_sync(FULLMASK, p, o);
        if (lane == 0) out[e] = p + bm2v;
    }
}

// ---------------------------------------------------------------------------
extern "C" void kernel_launch(void* const* d_in, const int* in_sizes, int n_in,
                              void* d_out, int out_size)
{
    const float* x     = (const float*)d_in[0];
    const int*   ei    = (const int*)  d_in[1];
    const float* ea    = (const float*)d_in[2];
    const float* W1    = (const float*)d_in[3];
    const float* b1    = (const float*)d_in[4];
    const float* gamma = (const float*)d_in[5];
    const float* beta  = (const float*)d_in[6];
    const float* W2    = (const float*)d_in[7];
    const float* b2    = (const float*)d_in[8];
    const float* Wm1   = (const float*)d_in[9];
    const float* bm1   = (const float*)d_in[10];
    const float* Wm2   = (const float*)d_in[11];
    const float* bm2   = (const float*)d_in[12];
    float* out = (float*)d_out;

    const int Nn = in_sizes[0] / HID;
    const int E  = in_sizes[1] / 2;
    const int* src = ei;
    const int* dst = ei + E;

    float *buf0, *buf1, *buf2, *dinv, *sum, *sumsq, *scale, *shift;
    int *cnt, *rowoff, *cursor, *csr_src;
    cudaGetSymbolAddress((void**)&buf0,    g_buf0);
    cudaGetSymbolAddress((void**)&buf1,    g_buf1);
    cudaGetSymbolAddress((void**)&buf2,    g_buf2);
    cudaGetSymbolAddress((void**)&dinv,    g_dinv);
    cudaGetSymbolAddress((void**)&sum,     g_sum);
    cudaGetSymbolAddress((void**)&sumsq,   g_sumsq);
    cudaGetSymbolAddress((void**)&scale,   g_scale);
    cudaGetSymbolAddress((void**)&shift,   g_shift);
    cudaGetSymbolAddress((void**)&cnt,     g_cnt);
    cudaGetSymbolAddress((void**)&rowoff,  g_rowoff);
    cudaGetSymbolAddress((void**)&cursor,  g_cursor);
    cudaGetSymbolAddress((void**)&csr_src, g_csr_src);

    const int SMEM = 2 * 128 * SMS * (int)sizeof(float);
    static int smem_set = 0;
    cudaFuncSetAttribute(gemm_tf32, cudaFuncAttributeMaxDynamicSharedMemorySize, SMEM);
    (void)smem_set;

    const int gN    = (Nn + 255) / 256;
    const int gE    = (E + 255) / 256;
    const int gGemm = (Nn + 127) / 128;
    const int gAgg  = (Nn * 32 + 255) / 256;

    // CSR build (by dst) + degrees
    zero_aux<<<gN, 256>>>(cnt, sum, sumsq, Nn);
    hist_dst<<<gE, 256>>>(dst, cnt, E);
    scan_offsets<<<1, 1024>>>(cnt, rowoff, cursor, dinv, Nn);
    fill_csr<<<gE, 256>>>(src, dst, cursor, csr_src, E);

    // conv1: h1 = x @ W1 ; agg1 = CSR gather + self-loop + b1
    gemm_tf32<<<gGemm, 256, SMEM>>>(x, W1, buf0, Nn, nullptr, nullptr);
    gcn_aggregate<<<gAgg, 256>>>(buf0, buf1, rowoff, csr_src, dinv, b1, Nn);

    // batchnorm stats (apply is fused into the next GEMM's A staging)
    bn_stats<<<512, 256>>>(buf1, sum, sumsq, Nn);
    bn_final<<<1, 128>>>(sum, sumsq, gamma, beta, scale, shift, Nn);

    // conv2: h2 = relu(bn(agg1)) @ W2 ; agg2
    gemm_tf32<<<gGemm, 256, SMEM>>>(buf1, W2, buf2, Nn, scale, shift);
    gcn_aggregate<<<gAgg, 256>>>(buf2, buf0, rowoff, csr_src, dinv, b2, Nn);

    // per-node projections for the edge MLP
    gemm_tf32<<<gGemm, 256, SMEM>>>(buf0, Wm1,             buf1, Nn, nullptr, nullptr);
    gemm_tf32<<<gGemm, 256, SMEM>>>(buf0, Wm1 + 128 * HID, buf2, Nn, nullptr, nullptr);

    // fused edge head
    edge_mlp<<<2048, 256>>>(buf1, buf2, src, dst, ea, Wm1 + 256 * HID,
                            bm1, Wm2, bm2, out, E);
}

// round 4
// speedup vs baseline: 1.3415x; 1.0992x over previous
#include <cuda_runtime.h>
#include <cstdint>

#define MAXN 50000
#define MAXE 800000
#define HID 128
#define FULLMASK 0xffffffffu

// ---- static scratch (no allocations allowed) ----
__device__ float g_buf0[(size_t)MAXN * HID];
__device__ float g_buf1[(size_t)MAXN * HID];
__device__ float g_buf2[(size_t)MAXN * HID];
__device__ float g_dinv[MAXN];
__device__ float g_sum[HID];
__device__ float g_sumsq[HID];
__device__ float g_scale[HID];
__device__ float g_shift[HID];
__device__ int   g_cnt[MAXN];
__device__ int   g_rowoff[MAXN + 1];
__device__ int   g_cursor[MAXN];
__device__ int   g_csr_src[MAXE];

// ---- packed f32x2 helpers (sm_103a FFMA2 path) ----
__device__ __forceinline__ uint64_t pack2(float lo, float hi)
{
    uint64_t r;
    asm("mov.b64 %0,{%1,%2};" : "=l"(r) : "f"(lo), "f"(hi));
    return r;
}
__device__ __forceinline__ void unpack2(uint64_t v, float& lo, float& hi)
{
    asm("mov.b64 {%0,%1},%2;" : "=f"(lo), "=f"(hi) : "l"(v));
}
__device__ __forceinline__ uint64_t fma2(uint64_t a, uint64_t b, uint64_t c)
{
    uint64_t d;
    asm("fma.rn.f32x2 %0,%1,%2,%3;" : "=l"(d) : "l"(a), "l"(b), "l"(c));
    return d;
}
__device__ __forceinline__ uint64_t add2(uint64_t a, uint64_t b)
{
    uint64_t d;
    asm("add.rn.f32x2 %0,%1,%2;" : "=l"(d) : "l"(a), "l"(b));
    return d;
}

// ---------------------------------------------------------------------------
__global__ void zero_aux(int* __restrict__ cnt, float* __restrict__ sum,
                         float* __restrict__ sumsq, int n)
{
    int i = blockIdx.x * blockDim.x + threadIdx.x;
    if (i < n) cnt[i] = 0;
    if (i < HID) { sum[i] = 0.0f; sumsq[i] = 0.0f; }
}

__global__ void hist_dst(const int* __restrict__ dst, int* __restrict__ cnt, int E)
{
    int i = blockIdx.x * blockDim.x + threadIdx.x;
    if (i < E) atomicAdd(&cnt[dst[i]], 1);
}

// Single-block coalesced tiled exclusive scan. Emits rowoff, cursor, dinv.
__global__ __launch_bounds__(1024)
void scan_offsets(const int* __restrict__ cnt, int* __restrict__ rowoff,
                  int* __restrict__ cursor, float* __restrict__ dinv, int n)
{
    __shared__ int warp_sums[32];
    const int t = threadIdx.x;
    const int lane = t & 31;
    const int w = t >> 5;
    int carry = 0;   // identical in every thread

    for (int base = 0; base < n; base += 1024) {
        int i = base + t;
        int c = (i < n) ? cnt[i] : 0;
        int v = c;
#pragma unroll
        for (int o = 1; o < 32; o <<= 1) {
            int u = __shfl_up_sync(FULLMASK, v, o);
            if (lane >= o) v += u;
        }
        if (lane == 31) warp_sums[w] = v;
        __syncthreads();
        if (w == 0) {
            int sv = warp_sums[lane];
#pragma unroll
            for (int o = 1; o < 32; o <<= 1) {
                int u = __shfl_up_sync(FULLMASK, sv, o);
                if (lane >= o) sv += u;
            }
            warp_sums[lane] = sv;
        }
        __syncthreads();
        int excl = carry + (w ? warp_sums[w - 1] : 0) + v - c;
        if (i < n) {
            rowoff[i] = excl;
            cursor[i] = excl;
            dinv[i]   = rsqrtf((float)c + 1.0f);
        }
        int tile_total = warp_sums[31];
        __syncthreads();
        carry += tile_total;
    }
    if (t == 0) rowoff[n] = carry;
}

__global__ void fill_csr(const int* __restrict__ src, const int* __restrict__ dst,
                         int* __restrict__ cursor, int* __restrict__ csr_src, int E)
{
    int e = blockIdx.x * blockDim.x + threadIdx.x;
    if (e < E) {
        int d = dst[e];
        int pos = atomicAdd(&cursor[d], 1);
        csr_src[pos] = src[e];
    }
}

// ---------------------------------------------------------------------------
// tf32 tensor-core GEMM with 3xTF32 error compensation.
#define SMS 136
#define WSS 264

__device__ __forceinline__ uint32_t f2tf32(float x)
{
    uint32_t r;
    asm("cvt.rna.tf32.f32 %0, %1;" : "=r"(r) : "f"(x));
    return r;
}

__device__ __forceinline__ void mma_tf32(float c[4], const uint32_t a[4],
                                         uint32_t b0, uint32_t b1)
{
    asm volatile(
        "mma.sync.aligned.m16n8k8.row.col.f32.tf32.tf32.f32 "
        "{%0,%1,%2,%3},{%4,%5,%6,%7},{%8,%9},{%0,%1,%2,%3};"
        : "+f"(c[0]), "+f"(c[1]), "+f"(c[2]), "+f"(c[3])
        : "r"(a[0]), "r"(a[1]), "r"(a[2]), "r"(a[3]), "r"(b0), "r"(b1));
}

// C[M,128] = f(A)[M,128] @ W[128,128]; f = optional scale/shift+relu.
__global__ __launch_bounds__(256)
void gemm_tf32(const float* __restrict__ A, const float* __restrict__ W,
               float* __restrict__ C, int M,
               const float* __restrict__ pre_scale,
               const float* __restrict__ pre_shift)
{
    extern __shared__ float smem[];
    float* As = smem;              // [128][SMS]
    float* Ws = smem + 128 * SMS;  // [128][SMS]

    const int tid = threadIdx.x;
    const int blockRow = blockIdx.x * 128;
    const bool do_pre = (pre_scale != nullptr);

#pragma unroll
    for (int t = 0; t < 16; t++) {
        int idx = tid + t * 256;
        int row = idx >> 5;
        int c4  = (idx & 31) * 4;
        int gr  = blockRow + row;
        float4 av = (gr < M) ? *(const float4*)(A + (size_t)gr * HID + c4)
                             : make_float4(0.f, 0.f, 0.f, 0.f);
        if (do_pre) {
            float4 sc = *(const float4*)(pre_scale + c4);
            float4 sh = *(const float4*)(pre_shift + c4);
            av.x = fmaxf(av.x * sc.x + sh.x, 0.f);
            av.y = fmaxf(av.y * sc.y + sh.y, 0.f);
            av.z = fmaxf(av.z * sc.z + sh.z, 0.f);
            av.w = fmaxf(av.w * sc.w + sh.w, 0.f);
        }
        *(float4*)(As + row * SMS + c4) = av;
        *(float4*)(Ws + row * SMS + c4) = *(const float4*)(W + (size_t)row * HID + c4);
    }
    __syncthreads();

    const int lane = tid & 31;
    const int warp = tid >> 5;
    const int g    = lane >> 2;
    const int tig  = lane & 3;
    const int wm   = (warp >> 1) * 32;
    const int wn   = (warp & 1) * 64;

    float c[2][8][4];
#pragma unroll
    for (int mt = 0; mt < 2; mt++)
#pragma unroll
        for (int nt = 0; nt < 8; nt++)
#pragma unroll
            for (int i = 0; i < 4; i++) c[mt][nt][i] = 0.f;

#pragma unroll
    for (int kt = 0; kt < 16; kt++) {
        const int k0 = kt * 8;
        uint32_t ahi[2][4], alo[2][4];
#pragma unroll
        for (int mt = 0; mt < 2; mt++) {
            int rb = wm + mt * 16;
            float a0 = As[(rb + g)     * SMS + k0 + tig];
            float a1 = As[(rb + g + 8) * SMS + k0 + tig];
            float a2 = As[(rb + g)     * SMS + k0 + tig + 4];
            float a3 = As[(rb + g + 8) * SMS + k0 + tig + 4];
            ahi[mt][0] = f2tf32(a0); alo[mt][0] = f2tf32(a0 - __uint_as_float(ahi[mt][0]));
            ahi[mt][1] = f2tf32(a1); alo[mt][1] = f2tf32(a1 - __uint_as_float(ahi[mt][1]));
            ahi[mt][2] = f2tf32(a2); alo[mt][2] = f2tf32(a2 - __uint_as_float(ahi[mt][2]));
            ahi[mt][3] = f2tf32(a3); alo[mt][3] = f2tf32(a3 - __uint_as_float(ahi[mt][3]));
        }
#pragma unroll
        for (int nt = 0; nt < 8; nt++) {
            int col = wn + nt * 8 + g;
            float b0 = Ws[(k0 + tig)     * SMS + col];
            float b1 = Ws[(k0 + tig + 4) * SMS + col];
            uint32_t bh0 = f2tf32(b0), bh1 = f2tf32(b1);
            uint32_t bl0 = f2tf32(b0 - __uint_as_float(bh0));
            uint32_t bl1 = f2tf32(b1 - __uint_as_float(bh1));
#pragma unroll
            for (int mt = 0; mt < 2; mt++) {
                mma_tf32(c[mt][nt], ahi[mt], bh0, bh1);
                mma_tf32(c[mt][nt], ahi[mt], bl0, bl1);
                mma_tf32(c[mt][nt], alo[mt], bh0, bh1);
            }
        }
    }

#pragma unroll
    for (int mt = 0; mt < 2; mt++) {
#pragma unroll
        for (int nt = 0; nt < 8; nt++) {
            int row0 = blockRow + wm + mt * 16 + g;
            int col0 = wn + nt * 8 + 2 * tig;
            if (row0 < M)
                *(float2*)(C + (size_t)row0 * HID + col0) = make_float2(c[mt][nt][0], c[mt][nt][1]);
            int row1 = row0 + 8;
            if (row1 < M)
                *(float2*)(C + (size_t)row1 * HID + col0) = make_float2(c[mt][nt][2], c[mt][nt][3]);
        }
    }
}

// Fused projection GEMM: C0 = A @ W[0:128], C1 = A @ W[128:256] (W stacked rows).
// 512 threads, block tile 128M x 256N, stages A once.
__global__ __launch_bounds__(512)
void gemm_proj(const float* __restrict__ A, const float* __restrict__ W,
               float* __restrict__ C0, float* __restrict__ C1, int M)
{
    extern __shared__ float smem[];
    float* As = smem;              // [128][SMS]
    float* Ws = smem + 128 * SMS;  // [128][WSS], cols 0..255

    const int tid = threadIdx.x;
    const int blockRow = blockIdx.x * 128;

#pragma unroll
    for (int t = 0; t < 8; t++) {
        int idx = tid + t * 512;
        int row = idx >> 5;
        int c4  = (idx & 31) * 4;
        int gr  = blockRow + row;
        float4 av = (gr < M) ? *(const float4*)(A + (size_t)gr * HID + c4)
                             : make_float4(0.f, 0.f, 0.f, 0.f);
        *(float4*)(As + row * SMS + c4) = av;
    }
#pragma unroll
    for (int t = 0; t < 16; t++) {
        int idx = tid + t * 512;           // 0..8191
        int r   = idx >> 5;                // stacked row 0..255
        int c4  = (idx & 31) * 4;
        int k    = r & 127;
        int half = r >> 7;
        *(float4*)(Ws + k * WSS + half * 128 + c4) =
            *(const float4*)(W + (size_t)r * HID + c4);
    }
    __syncthreads();

    const int lane = tid & 31;
    const int warp = tid >> 5;             // 0..15
    const int g    = lane >> 2;
    const int tig  = lane & 3;
    const int wm   = (warp >> 2) * 32;     // 0,32,64,96
    const int wn   = (warp & 3) * 64;      // 0,64,128,192

    float c[2][8][4];
#pragma unroll
    for (int mt = 0; mt < 2; mt++)
#pragma unroll
        for (int nt = 0; nt < 8; nt++)
#pragma unroll
            for (int i = 0; i < 4; i++) c[mt][nt][i] = 0.f;

#pragma unroll
    for (int kt = 0; kt < 16; kt++) {
        const int k0 = kt * 8;
        uint32_t ahi[2][4], alo[2][4];
#pragma unroll
        for (int mt = 0; mt < 2; mt++) {
            int rb = wm + mt * 16;
            float a0 = As[(rb + g)     * SMS + k0 + tig];
            float a1 = As[(rb + g + 8) * SMS + k0 + tig];
            float a2 = As[(rb + g)     * SMS + k0 + tig + 4];
            float a3 = As[(rb + g + 8) * SMS + k0 + tig + 4];
            ahi[mt][0] = f2tf32(a0); alo[mt][0] = f2tf32(a0 - __uint_as_float(ahi[mt][0]));
            ahi[mt][1] = f2tf32(a1); alo[mt][1] = f2tf32(a1 - __uint_as_float(ahi[mt][1]));
            ahi[mt][2] = f2tf32(a2); alo[mt][2] = f2tf32(a2 - __uint_as_float(ahi[mt][2]));
            ahi[mt][3] = f2tf32(a3); alo[mt][3] = f2tf32(a3 - __uint_as_float(ahi[mt][3]));
        }
#pragma unroll
        for (int nt = 0; nt < 8; nt++) {
            int col = wn + nt * 8 + g;
            float b0 = Ws[(k0 + tig)     * WSS + col];
            float b1 = Ws[(k0 + tig + 4) * WSS + col];
            uint32_t bh0 = f2tf32(b0), bh1 = f2tf32(b1);
            uint32_t bl0 = f2tf32(b0 - __uint_as_float(bh0));
            uint32_t bl1 = f2tf32(b1 - __uint_as_float(bh1));
#pragma unroll
            for (int mt = 0; mt < 2; mt++) {
                mma_tf32(c[mt][nt], ahi[mt], bh0, bh1);
                mma_tf32(c[mt][nt], ahi[mt], bl0, bl1);
                mma_tf32(c[mt][nt], alo[mt], bh0, bh1);
            }
        }
    }

    float* Cb = (wn < 128) ? C0 : C1;
    const int cbase = (wn < 128) ? wn : wn - 128;
#pragma unroll
    for (int mt = 0; mt < 2; mt++) {
#pragma unroll
        for (int nt = 0; nt < 8; nt++) {
            int row0 = blockRow + wm + mt * 16 + g;
            int col0 = cbase + nt * 8 + 2 * tig;
            if (row0 < M)
                *(float2*)(Cb + (size_t)row0 * HID + col0) = make_float2(c[mt][nt][0], c[mt][nt][1]);
            int row1 = row0 + 8;
            if (row1 < M)
                *(float2*)(Cb + (size_t)row1 * HID + col0) = make_float2(c[mt][nt][2], c[mt][nt][3]);
        }
    }
}

// ---------------------------------------------------------------------------
// agg[n,:] = sum_{e: dst=n} h[src_e,:]*dinv[src]*dinv[n] + h[n,:]*dinv[n]^2 + b
// one warp per dst node; batch-loads 32 (index, weight) pairs; f32x2 FMAs.
__global__ __launch_bounds__(256)
void gcn_aggregate(const float* __restrict__ h, float* __restrict__ agg,
                   const int* __restrict__ rowoff, const int* __restrict__ csr_src,
                   const float* __restrict__ dinv, const float* __restrict__ bias,
                   int Nn)
{
    int lane = threadIdx.x & 31;
    int n = (blockIdx.x * blockDim.x + threadIdx.x) >> 5;
    if (n >= Nn) return;
    int c4 = lane * 4;

    float din = dinv[n];
    float wsl = din * din;
    ulonglong2 hv = *(const ulonglong2*)(h + (size_t)n * HID + c4);
    ulonglong2 bb = *(const ulonglong2*)(bias + c4);
    uint64_t wsl2 = pack2(wsl, wsl);
    uint64_t acc0 = fma2(hv.x, wsl2, bb.x);
    uint64_t acc1 = fma2(hv.y, wsl2, bb.y);

    int beg = rowoff[n], end = rowoff[n + 1];
    for (int base = beg; base < end; base += 32) {
        int m = end - base;
        int s = 0;
        float ww = 0.f;
        if (lane < m) {
            s = __ldg(&csr_src[base + lane]);
            ww = dinv[s] * din;
        }
        int iters = min(m, 32);
#pragma unroll 4
        for (int j = 0; j < iters; j++) {
            int   sj = __shfl_sync(FULLMASK, s,  j);
            float wj = __shfl_sync(FULLMASK, ww, j);
            uint64_t wj2 = pack2(wj, wj);
            ulonglong2 rv = *(const ulonglong2*)(h + (size_t)sj * HID + c4);
            acc0 = fma2(rv.x, wj2, acc0);
            acc1 = fma2(rv.y, wj2, acc1);
        }
    }
    ulonglong2 outv;
    outv.x = acc0;
    outv.y = acc1;
    *(ulonglong2*)(agg + (size_t)n * HID + c4) = outv;
}

// ---------------------------------------------------------------------------
__global__ __launch_bounds__(256)
void bn_stats(const float* __restrict__ z, float* __restrict__ sum,
              float* __restrict__ sumsq, int Nn)
{
    int c    = threadIdx.x & 127;
    int half = threadIdx.x >> 7;
    float s = 0.f, q = 0.f;
    for (int r = blockIdx.x * 2 + half; r < Nn; r += gridDim.x * 2) {
        float v = z[(size_t)r * HID + c];
        s += v;
        q += v * v;
    }
    __shared__ float sh[256];
    sh[threadIdx.x] = s;
    __syncthreads();
    if (half == 0) atomicAdd(&sum[c], sh[c] + sh[c + 128]);
    __syncthreads();
    sh[threadIdx.x] = q;
    __syncthreads();
    if (half == 0) atomicAdd(&sumsq[c], sh[c] + sh[c + 128]);
}

__global__ void bn_final(const float* __restrict__ sum, const float* __restrict__ sumsq,
                         const float* __restrict__ gamma, const float* __restrict__ beta,
                         float* __restrict__ scale, float* __restrict__ shift, int Nn)
{
    int i = threadIdx.x;
    if (i < HID) {
        float invN = 1.0f / (float)Nn;
        float mean = sum[i] * invN;
        float var  = sumsq[i] * invN - mean * mean;
        float sc   = gamma[i] * rsqrtf(var + 1e-5f);
        scale[i] = sc;
        shift[i] = beta[i] - mean * sc;
    }
}

// ---------------------------------------------------------------------------
// out[e] = relu(A[src] + B[dst] + edge_attr[e]@We + bm1) . Wm2 + bm2
// One warp per edge; We in registers as packed f32x2; FFMA2 inner loop.
__global__ __launch_bounds__(256)
void edge_mlp(const float* __restrict__ A, const float* __restrict__ B,
              const int* __restrict__ src, const int* __restrict__ dst,
              const float* __restrict__ ea, const float* __restrict__ We,  // [16,128]
              const float* __restrict__ bm1, const float* __restrict__ Wm2,
              const float* __restrict__ bm2, float* __restrict__ out, int E)
{
    int lane = threadIdx.x & 31;
    int warp = (blockIdx.x * blockDim.x + threadIdx.x) >> 5;
    int nw   = (gridDim.x * blockDim.x) >> 5;
    int c4   = lane * 4;

    uint64_t wp0[16], wp1[16];
#pragma unroll
    for (int k = 0; k < 16; k++) {
        ulonglong2 wv = *(const ulonglong2*)(We + (size_t)k * HID + c4);
        wp0[k] = wv.x;
        wp1[k] = wv.y;
    }
    ulonglong2 bv2 = *(const ulonglong2*)(bm1 + c4);
    const uint64_t bias0 = bv2.x, bias1 = bv2.y;
    float4 w2 = *(const float4*)(Wm2 + c4);
    const float bm2v = __ldg(bm2);

    for (int e = warp; e < E; e += nw) {
        int s = __ldg(&src[e]);
        int d = __ldg(&dst[e]);
        ulonglong2 av = *(const ulonglong2*)(A + (size_t)s * HID + c4);
        ulonglong2 bvv = *(const ulonglong2*)(B + (size_t)d * HID + c4);
        uint64_t acc0 = add2(add2(av.x, bvv.x), bias0);
        uint64_t acc1 = add2(add2(av.y, bvv.y), bias1);

        const float4* eap = (const float4*)(ea + (size_t)e * 16);
#pragma unroll
        for (int gq = 0; gq < 4; gq++) {
            float4 e4 = __ldg(&eap[gq]);   // uniform across warp -> broadcast
            uint64_t ex;
            ex = pack2(e4.x, e4.x);
            acc0 = fma2(wp0[gq * 4 + 0], ex, acc0);
            acc1 = fma2(wp1[gq * 4 + 0], ex, acc1);
            ex = pack2(e4.y, e4.y);
            acc0 = fma2(wp0[gq * 4 + 1], ex, acc0);
            acc1 = fma2(wp1[gq * 4 + 1], ex, acc1);
            ex = pack2(e4.z, e4.z);
            acc0 = fma2(wp0[gq * 4 + 2], ex, acc0);
            acc1 = fma2(wp1[gq * 4 + 2], ex, acc1);
            ex = pack2(e4.w, e4.w);
            acc0 = fma2(wp0[gq * 4 + 3], ex, acc0);
            acc1 = fma2(wp1[gq * 4 + 3], ex, acc1);
        }
        float f0, f1, f2, f3;
        unpack2(acc0, f0, f1);
        unpack2(acc1, f2, f3);
        f0 = fmaxf(f0, 0.f);
        f1 = fmaxf(f1, 0.f);
        f2 = fmaxf(f2, 0.f);
        f3 = fmaxf(f3, 0.f);

        float p = f0 * w2.x + f1 * w2.y + f2 * w2.z + f3 * w2.w;
#pragma unroll
        for (int o = 16; o; o >>= 1) p += __shfl_xor_sync(FULLMASK, p, o);
        if (lane == 0) out[e] = p + bm2v;
    }
}

// ---------------------------------------------------------------------------
extern "C" void kernel_launch(void* const* d_in, const int* in_sizes, int n_in,
                              void* d_out, int out_size)
{
    const float* x     = (const float*)d_in[0];
    const int*   ei    = (const int*)  d_in[1];
    const float* ea    = (const float*)d_in[2];
    const float* W1    = (const float*)d_in[3];
    const float* b1    = (const float*)d_in[4];
    const float* gamma = (const float*)d_in[5];
    const float* beta  = (const float*)d_in[6];
    const float* W2    = (const float*)d_in[7];
    const float* b2    = (const float*)d_in[8];
    const float* Wm1   = (const float*)d_in[9];
    const float* bm1   = (const float*)d_in[10];
    const float* Wm2   = (const float*)d_in[11];
    const float* bm2   = (const float*)d_in[12];
    float* out = (float*)d_out;

    const int Nn = in_sizes[0] / HID;
    const int E  = in_sizes[1] / 2;
    const int* src = ei;
    const int* dst = ei + E;

    float *buf0, *buf1, *buf2, *dinv, *sum, *sumsq, *scale, *shift;
    int *cnt, *rowoff, *cursor, *csr_src;
    cudaGetSymbolAddress((void**)&buf0,    g_buf0);
    cudaGetSymbolAddress((void**)&buf1,    g_buf1);
    cudaGetSymbolAddress((void**)&buf2,    g_buf2);
    cudaGetSymbolAddress((void**)&dinv,    g_dinv);
    cudaGetSymbolAddress((void**)&sum,     g_sum);
    cudaGetSymbolAddress((void**)&sumsq,   g_sumsq);
    cudaGetSymbolAddress((void**)&scale,   g_scale);
    cudaGetSymbolAddress((void**)&shift,   g_shift);
    cudaGetSymbolAddress((void**)&cnt,     g_cnt);
    cudaGetSymbolAddress((void**)&rowoff,  g_rowoff);
    cudaGetSymbolAddress((void**)&cursor,  g_cursor);
    cudaGetSymbolAddress((void**)&csr_src, g_csr_src);

    const int SMEM  = 2 * 128 * SMS * (int)sizeof(float);
    const int SMEMP = 128 * (SMS + WSS) * (int)sizeof(float);
    cudaFuncSetAttribute(gemm_tf32, cudaFuncAttributeMaxDynamicSharedMemorySize, SMEM);
    cudaFuncSetAttribute(gemm_proj, cudaFuncAttributeMaxDynamicSharedMemorySize, SMEMP);

    const int gN    = (Nn + 255) / 256;
    const int gE    = (E + 255) / 256;
    const int gGemm = (Nn + 127) / 128;
    const int gAgg  = (Nn * 32 + 255) / 256;

    // CSR build (by dst) + degrees
    zero_aux<<<gN, 256>>>(cnt, sum, sumsq, Nn);
    hist_dst<<<gE, 256>>>(dst, cnt, E);
    scan_offsets<<<1, 1024>>>(cnt, rowoff, cursor, dinv, Nn);
    fill_csr<<<gE, 256>>>(src, dst, cursor, csr_src, E);

    // conv1: h1 = x @ W1 ; agg1 = CSR gather + self-loop + b1
    gemm_tf32<<<gGemm, 256, SMEM>>>(x, W1, buf0, Nn, nullptr, nullptr);
    gcn_aggregate<<<gAgg, 256>>>(buf0, buf1, rowoff, csr_src, dinv, b1, Nn);

    // batchnorm stats (apply fused into next GEMM's A staging)
    bn_stats<<<512, 256>>>(buf1, sum, sumsq, Nn);
    bn_final<<<1, 128>>>(sum, sumsq, gamma, beta, scale, shift, Nn);

    // conv2: h2 = relu(bn(agg1)) @ W2 ; agg2
    gemm_tf32<<<gGemm, 256, SMEM>>>(buf1, W2, buf2, Nn, scale, shift);
    gcn_aggregate<<<gAgg, 256>>>(buf2, buf0, rowoff, csr_src, dinv, b2, Nn);

    // fused per-node projections: buf1 = z2@Wm1[0:128], buf2 = z2@Wm1[128:256]
    gemm_proj<<<gGemm, 512, SMEMP>>>(buf0, Wm1, buf1, buf2, Nn);

    // fused edge head
    edge_mlp<<<2048, 256>>>(buf1, buf2, src, dst, ea, Wm1 + 256 * HID,
                            bm1, Wm2, bm2, out, E);
}

// round 5
// speedup vs baseline: 1.7904x; 1.3347x over previous
#include <cuda_runtime.h>
#include <cuda_fp16.h>
#include <cstdint>

#define MAXN 50000
#define MAXE 800000
#define HID 128
#define FULLMASK 0xffffffffu

// ---- static scratch (no allocations allowed) ----
__device__ float  g_buf0[(size_t)MAXN * HID];   // fp32 aggregate outputs
__device__ __half g_h16 [(size_t)MAXN * HID];   // fp16 h1 then h2 (gather target)
__device__ __half g_A16 [(size_t)MAXN * HID];   // fp16 edge-head src projection
__device__ __half g_B16 [(size_t)MAXN * HID];   // fp16 edge-head dst projection
__device__ float  g_dinv[MAXN];
__device__ float  g_sum[HID];
__device__ float  g_sumsq[HID];
__device__ float  g_scale[HID];
__device__ float  g_shift[HID];
__device__ int    g_cnt[MAXN];
__device__ int    g_rowoff[MAXN + 1];
__device__ int    g_cursor[MAXN];
__device__ int    g_csr_src[MAXE];

// ---- packed f32x2 helpers (sm_103a FFMA2 path) ----
__device__ __forceinline__ uint64_t pack2(float lo, float hi)
{
    uint64_t r;
    asm("mov.b64 %0,{%1,%2};" : "=l"(r) : "f"(lo), "f"(hi));
    return r;
}
__device__ __forceinline__ void unpack2(uint64_t v, float& lo, float& hi)
{
    asm("mov.b64 {%0,%1},%2;" : "=f"(lo), "=f"(hi) : "l"(v));
}
__device__ __forceinline__ uint64_t fma2(uint64_t a, uint64_t b, uint64_t c)
{
    uint64_t d;
    asm("fma.rn.f32x2 %0,%1,%2,%3;" : "=l"(d) : "l"(a), "l"(b), "l"(c));
    return d;
}

// ---------------------------------------------------------------------------
__global__ void zero_aux(int* __restrict__ cnt, float* __restrict__ sum,
                         float* __restrict__ sumsq, int n)
{
    int i = blockIdx.x * blockDim.x + threadIdx.x;
    if (i < n) cnt[i] = 0;
    if (i < HID) { sum[i] = 0.0f; sumsq[i] = 0.0f; }
}

__global__ void hist_dst(const int* __restrict__ dst, int* __restrict__ cnt, int E)
{
    int i = blockIdx.x * blockDim.x + threadIdx.x;
    if (i < E) atomicAdd(&cnt[dst[i]], 1);
}

// Single-block coalesced tiled exclusive scan. Emits rowoff, cursor, dinv.
__global__ __launch_bounds__(1024)
void scan_offsets(const int* __restrict__ cnt, int* __restrict__ rowoff,
                  int* __restrict__ cursor, float* __restrict__ dinv, int n)
{
    __shared__ int warp_sums[32];
    const int t = threadIdx.x;
    const int lane = t & 31;
    const int w = t >> 5;
    int carry = 0;

    for (int base = 0; base < n; base += 1024) {
        int i = base + t;
        int c = (i < n) ? cnt[i] : 0;
        int v = c;
#pragma unroll
        for (int o = 1; o < 32; o <<= 1) {
            int u = __shfl_up_sync(FULLMASK, v, o);
            if (lane >= o) v += u;
        }
        if (lane == 31) warp_sums[w] = v;
        __syncthreads();
        if (w == 0) {
            int sv = warp_sums[lane];
#pragma unroll
            for (int o = 1; o < 32; o <<= 1) {
                int u = __shfl_up_sync(FULLMASK, sv, o);
                if (lane >= o) sv += u;
            }
            warp_sums[lane] = sv;
        }
        __syncthreads();
        int excl = carry + (w ? warp_sums[w - 1] : 0) + v - c;
        if (i < n) {
            rowoff[i] = excl;
            cursor[i] = excl;
            dinv[i]   = rsqrtf((float)c + 1.0f);
        }
        int tile_total = warp_sums[31];
        __syncthreads();
        carry += tile_total;
    }
    if (t == 0) rowoff[n] = carry;
}

__global__ void fill_csr(const int* __restrict__ src, const int* __restrict__ dst,
                         int* __restrict__ cursor, int* __restrict__ csr_src, int E)
{
    int e = blockIdx.x * blockDim.x + threadIdx.x;
    if (e < E) {
        int d = dst[e];
        int pos = atomicAdd(&cursor[d], 1);
        csr_src[pos] = src[e];
    }
}

// ---------------------------------------------------------------------------
// tf32 tensor-core GEMM with 3xTF32 error compensation. Output fp16.
#define SMS 136
#define WSS 264

__device__ __forceinline__ uint32_t f2tf32(float x)
{
    uint32_t r;
    asm("cvt.rna.tf32.f32 %0, %1;" : "=r"(r) : "f"(x));
    return r;
}

__device__ __forceinline__ void mma_tf32(float c[4], const uint32_t a[4],
                                         uint32_t b0, uint32_t b1)
{
    asm volatile(
        "mma.sync.aligned.m16n8k8.row.col.f32.tf32.tf32.f32 "
        "{%0,%1,%2,%3},{%4,%5,%6,%7},{%8,%9},{%0,%1,%2,%3};"
        : "+f"(c[0]), "+f"(c[1]), "+f"(c[2]), "+f"(c[3])
        : "r"(a[0]), "r"(a[1]), "r"(a[2]), "r"(a[3]), "r"(b0), "r"(b1));
}

// C16[M,128] = f(A)[M,128] @ W[128,128]; f = optional scale/shift+relu.
__global__ __launch_bounds__(256)
void gemm_tf32(const float* __restrict__ A, const float* __restrict__ W,
               __half* __restrict__ C, int M,
               const float* __restrict__ pre_scale,
               const float* __restrict__ pre_shift)
{
    extern __shared__ float smem[];
    float* As = smem;              // [128][SMS]
    float* Ws = smem + 128 * SMS;  // [128][SMS]

    const int tid = threadIdx.x;
    const int blockRow = blockIdx.x * 128;
    const bool do_pre = (pre_scale != nullptr);

#pragma unroll
    for (int t = 0; t < 16; t++) {
        int idx = tid + t * 256;
        int row = idx >> 5;
        int c4  = (idx & 31) * 4;
        int gr  = blockRow + row;
        float4 av = (gr < M) ? *(const float4*)(A + (size_t)gr * HID + c4)
                             : make_float4(0.f, 0.f, 0.f, 0.f);
        if (do_pre) {
            float4 sc = *(const float4*)(pre_scale + c4);
            float4 sh = *(const float4*)(pre_shift + c4);
            av.x = fmaxf(av.x * sc.x + sh.x, 0.f);
            av.y = fmaxf(av.y * sc.y + sh.y, 0.f);
            av.z = fmaxf(av.z * sc.z + sh.z, 0.f);
            av.w = fmaxf(av.w * sc.w + sh.w, 0.f);
        }
        *(float4*)(As + row * SMS + c4) = av;
        *(float4*)(Ws + row * SMS + c4) = *(const float4*)(W + (size_t)row * HID + c4);
    }
    __syncthreads();

    const int lane = tid & 31;
    const int warp = tid >> 5;
    const int g    = lane >> 2;
    const int tig  = lane & 3;
    const int wm   = (warp >> 1) * 32;
    const int wn   = (warp & 1) * 64;

    float c[2][8][4];
#pragma unroll
    for (int mt = 0; mt < 2; mt++)
#pragma unroll
        for (int nt = 0; nt < 8; nt++)
#pragma unroll
            for (int i = 0; i < 4; i++) c[mt][nt][i] = 0.f;

#pragma unroll
    for (int kt = 0; kt < 16; kt++) {
        const int k0 = kt * 8;
        uint32_t ahi[2][4], alo[2][4];
#pragma unroll
        for (int mt = 0; mt < 2; mt++) {
            int rb = wm + mt * 16;
            float a0 = As[(rb + g)     * SMS + k0 + tig];
            float a1 = As[(rb + g + 8) * SMS + k0 + tig];
            float a2 = As[(rb + g)     * SMS + k0 + tig + 4];
            float a3 = As[(rb + g + 8) * SMS + k0 + tig + 4];
            ahi[mt][0] = f2tf32(a0); alo[mt][0] = f2tf32(a0 - __uint_as_float(ahi[mt][0]));
            ahi[mt][1] = f2tf32(a1); alo[mt][1] = f2tf32(a1 - __uint_as_float(ahi[mt][1]));
            ahi[mt][2] = f2tf32(a2); alo[mt][2] = f2tf32(a2 - __uint_as_float(ahi[mt][2]));
            ahi[mt][3] = f2tf32(a3); alo[mt][3] = f2tf32(a3 - __uint_as_float(ahi[mt][3]));
        }
#pragma unroll
        for (int nt = 0; nt < 8; nt++) {
            int col = wn + nt * 8 + g;
            float b0 = Ws[(k0 + tig)     * SMS + col];
            float b1 = Ws[(k0 + tig + 4) * SMS + col];
            uint32_t bh0 = f2tf32(b0), bh1 = f2tf32(b1);
            uint32_t bl0 = f2tf32(b0 - __uint_as_float(bh0));
            uint32_t bl1 = f2tf32(b1 - __uint_as_float(bh1));
#pragma unroll
            for (int mt = 0; mt < 2; mt++) {
                mma_tf32(c[mt][nt], ahi[mt], bh0, bh1);
                mma_tf32(c[mt][nt], ahi[mt], bl0, bl1);
                mma_tf32(c[mt][nt], alo[mt], bh0, bh1);
            }
        }
    }

#pragma unroll
    for (int mt = 0; mt < 2; mt++) {
#pragma unroll
        for (int nt = 0; nt < 8; nt++) {
            int row0 = blockRow + wm + mt * 16 + g;
            int col0 = wn + nt * 8 + 2 * tig;
            if (row0 < M)
                *(__half2*)(C + (size_t)row0 * HID + col0) =
                    __floats2half2_rn(c[mt][nt][0], c[mt][nt][1]);
            int row1 = row0 + 8;
            if (row1 < M)
                *(__half2*)(C + (size_t)row1 * HID + col0) =
                    __floats2half2_rn(c[mt][nt][2], c[mt][nt][3]);
        }
    }
}

// Fused projection GEMM: C0 = A @ W[0:128], C1 = A @ W[128:256], fp16 outputs.
__global__ __launch_bounds__(512)
void gemm_proj(const float* __restrict__ A, const float* __restrict__ W,
               __half* __restrict__ C0, __half* __restrict__ C1, int M)
{
    extern __shared__ float smem[];
    float* As = smem;              // [128][SMS]
    float* Ws = smem + 128 * SMS;  // [128][WSS]

    const int tid = threadIdx.x;
    const int blockRow = blockIdx.x * 128;

#pragma unroll
    for (int t = 0; t < 8; t++) {
        int idx = tid + t * 512;
        int row = idx >> 5;
        int c4  = (idx & 31) * 4;
        int gr  = blockRow + row;
        float4 av = (gr < M) ? *(const float4*)(A + (size_t)gr * HID + c4)
                             : make_float4(0.f, 0.f, 0.f, 0.f);
        *(float4*)(As + row * SMS + c4) = av;
    }
#pragma unroll
    for (int t = 0; t < 16; t++) {
        int idx = tid + t * 512;
        int r   = idx >> 5;
        int c4  = (idx & 31) * 4;
        int k    = r & 127;
        int half = r >> 7;
        *(float4*)(Ws + k * WSS + half * 128 + c4) =
            *(const float4*)(W + (size_t)r * HID + c4);
    }
    __syncthreads();

    const int lane = tid & 31;
    const int warp = tid >> 5;
    const int g    = lane >> 2;
    const int tig  = lane & 3;
    const int wm   = (warp >> 2) * 32;
    const int wn   = (warp & 3) * 64;

    float c[2][8][4];
#pragma unroll
    for (int mt = 0; mt < 2; mt++)
#pragma unroll
        for (int nt = 0; nt < 8; nt++)
#pragma unroll
            for (int i = 0; i < 4; i++) c[mt][nt][i] = 0.f;

#pragma unroll
    for (int kt = 0; kt < 16; kt++) {
        const int k0 = kt * 8;
        uint32_t ahi[2][4], alo[2][4];
#pragma unroll
        for (int mt = 0; mt < 2; mt++) {
            int rb = wm + mt * 16;
            float a0 = As[(rb + g)     * SMS + k0 + tig];
            float a1 = As[(rb + g + 8) * SMS + k0 + tig];
            float a2 = As[(rb + g)     * SMS + k0 + tig + 4];
            float a3 = As[(rb + g + 8) * SMS + k0 + tig + 4];
            ahi[mt][0] = f2tf32(a0); alo[mt][0] = f2tf32(a0 - __uint_as_float(ahi[mt][0]));
            ahi[mt][1] = f2tf32(a1); alo[mt][1] = f2tf32(a1 - __uint_as_float(ahi[mt][1]));
            ahi[mt][2] = f2tf32(a2); alo[mt][2] = f2tf32(a2 - __uint_as_float(ahi[mt][2]));
            ahi[mt][3] = f2tf32(a3); alo[mt][3] = f2tf32(a3 - __uint_as_float(ahi[mt][3]));
        }
#pragma unroll
        for (int nt = 0; nt < 8; nt++) {
            int col = wn + nt * 8 + g;
            float b0 = Ws[(k0 + tig)     * WSS + col];
            float b1 = Ws[(k0 + tig + 4) * WSS + col];
            uint32_t bh0 = f2tf32(b0), bh1 = f2tf32(b1);
            uint32_t bl0 = f2tf32(b0 - __uint_as_float(bh0));
            uint32_t bl1 = f2tf32(b1 - __uint_as_float(bh1));
#pragma unroll
            for (int mt = 0; mt < 2; mt++) {
                mma_tf32(c[mt][nt], ahi[mt], bh0, bh1);
                mma_tf32(c[mt][nt], ahi[mt], bl0, bl1);
                mma_tf32(c[mt][nt], alo[mt], bh0, bh1);
            }
        }
    }

    __half* Cb = (wn < 128) ? C0 : C1;
    const int cbase = (wn < 128) ? wn : wn - 128;
#pragma unroll
    for (int mt = 0; mt < 2; mt++) {
#pragma unroll
        for (int nt = 0; nt < 8; nt++) {
            int row0 = blockRow + wm + mt * 16 + g;
            int col0 = cbase + nt * 8 + 2 * tig;
            if (row0 < M)
                *(__half2*)(Cb + (size_t)row0 * HID + col0) =
                    __floats2half2_rn(c[mt][nt][0], c[mt][nt][1]);
            int row1 = row0 + 8;
            if (row1 < M)
                *(__half2*)(Cb + (size_t)row1 * HID + col0) =
                    __floats2half2_rn(c[mt][nt][2], c[mt][nt][3]);
        }
    }
}

// ---------------------------------------------------------------------------
// agg[n,:] = sum_{e: dst=n} h[src_e,:]*dinv[src]*dinv[n] + h[n,:]*dinv[n]^2 + b
// fp16 gathers, fp32 (f32x2) accumulation. One warp per dst node.
__global__ __launch_bounds__(256)
void gcn_aggregate(const __half* __restrict__ h, float* __restrict__ agg,
                   const int* __restrict__ rowoff, const int* __restrict__ csr_src,
                   const float* __restrict__ dinv, const float* __restrict__ bias,
                   int Nn)
{
    int lane = threadIdx.x & 31;
    int n = (blockIdx.x * blockDim.x + threadIdx.x) >> 5;
    if (n >= Nn) return;
    int c4 = lane * 4;

    float din = dinv[n];
    float wsl = din * din;
    uint2 hv = *(const uint2*)(h + (size_t)n * HID + c4);
    float2 h0 = __half22float2(*(const __half2*)&hv.x);
    float2 h1 = __half22float2(*(const __half2*)&hv.y);
    float4 bb = *(const float4*)(bias + c4);
    uint64_t acc0 = pack2(h0.x * wsl + bb.x, h0.y * wsl + bb.y);
    uint64_t acc1 = pack2(h1.x * wsl + bb.z, h1.y * wsl + bb.w);

    int beg = rowoff[n], end = rowoff[n + 1];
    for (int base = beg; base < end; base += 32) {
        int m = end - base;
        int s = 0;
        float ww = 0.f;
        if (lane < m) {
            s = __ldg(&csr_src[base + lane]);
            ww = dinv[s] * din;
        }
        int iters = min(m, 32);
#pragma unroll 4
        for (int j = 0; j < iters; j++) {
            int   sj = __shfl_sync(FULLMASK, s,  j);
            float wj = __shfl_sync(FULLMASK, ww, j);
            uint64_t wj2 = pack2(wj, wj);
            uint2 rv = *(const uint2*)(h + (size_t)sj * HID + c4);
            float2 r0 = __half22float2(*(const __half2*)&rv.x);
            float2 r1 = __half22float2(*(const __half2*)&rv.y);
            acc0 = fma2(pack2(r0.x, r0.y), wj2, acc0);
            acc1 = fma2(pack2(r1.x, r1.y), wj2, acc1);
        }
    }
    ulonglong2 outv;
    outv.x = acc0;
    outv.y = acc1;
    *(ulonglong2*)(agg + (size_t)n * HID + c4) = outv;
}

// ---------------------------------------------------------------------------
__global__ __launch_bounds__(256)
void bn_stats(const float* __restrict__ z, float* __restrict__ sum,
              float* __restrict__ sumsq, int Nn)
{
    int c    = threadIdx.x & 127;
    int half = threadIdx.x >> 7;
    float s = 0.f, q = 0.f;
    for (int r = blockIdx.x * 2 + half; r < Nn; r += gridDim.x * 2) {
        float v = z[(size_t)r * HID + c];
        s += v;
        q += v * v;
    }
    __shared__ float sh[256];
    sh[threadIdx.x] = s;
    __syncthreads();
    if (half == 0) atomicAdd(&sum[c], sh[c] + sh[c + 128]);
    __syncthreads();
    sh[threadIdx.x] = q;
    __syncthreads();
    if (half == 0) atomicAdd(&sumsq[c], sh[c] + sh[c + 128]);
}

__global__ void bn_final(const float* __restrict__ sum, const float* __restrict__ sumsq,
                         const float* __restrict__ gamma, const float* __restrict__ beta,
                         float* __restrict__ scale, float* __restrict__ shift, int Nn)
{
    int i = threadIdx.x;
    if (i < HID) {
        float invN = 1.0f / (float)Nn;
        float mean = sum[i] * invN;
        float var  = sumsq[i] * invN - mean * mean;
        float sc   = gamma[i] * rsqrtf(var + 1e-5f);
        scale[i] = sc;
        shift[i] = beta[i] - mean * sc;
    }
}

// ---------------------------------------------------------------------------
// out[e] = relu(A[src] + B[dst] + edge_attr[e]@We + bm1) . Wm2 + bm2
// fp16 A/B gathers; batched index loads; coalesced output stores.
__global__ __launch_bounds__(256)
void edge_mlp(const __half* __restrict__ A, const __half* __restrict__ B,
              const int* __restrict__ src, const int* __restrict__ dst,
              const float* __restrict__ ea, const float* __restrict__ We,  // [16,128]
              const float* __restrict__ bm1, const float* __restrict__ Wm2,
              const float* __restrict__ bm2, float* __restrict__ out, int E)
{
    int lane = threadIdx.x & 31;
    int warp = (blockIdx.x * blockDim.x + threadIdx.x) >> 5;
    int nw   = (gridDim.x * blockDim.x) >> 5;
    int c4   = lane * 4;

    uint64_t wp0[16], wp1[16];
#pragma unroll
    for (int k = 0; k < 16; k++) {
        ulonglong2 wv = *(const ulonglong2*)(We + (size_t)k * HID + c4);
        wp0[k] = wv.x;
        wp1[k] = wv.y;
    }
    float4 bv = *(const float4*)(bm1 + c4);
    float4 w2 = *(const float4*)(Wm2 + c4);
    const float bm2v = __ldg(bm2);

    for (int base = warp * 32; base < E; base += nw * 32) {
        int m = min(32, E - base);
        int s = 0, d = 0;
        if (lane < m) {
            s = __ldg(&src[base + lane]);
            d = __ldg(&dst[base + lane]);
        }
        float res = 0.f;
        for (int j = 0; j < m; j++) {
            int sj = __shfl_sync(FULLMASK, s, j);
            int dj = __shfl_sync(FULLMASK, d, j);
            uint2 av2 = *(const uint2*)(A + (size_t)sj * HID + c4);
            uint2 bv2 = *(const uint2*)(B + (size_t)dj * HID + c4);
            float2 a0 = __half22float2(*(const __half2*)&av2.x);
            float2 a1 = __half22float2(*(const __half2*)&av2.y);
            float2 b0 = __half22float2(*(const __half2*)&bv2.x);
            float2 b1 = __half22float2(*(const __half2*)&bv2.y);
            uint64_t acc0 = pack2(a0.x + b0.x + bv.x, a0.y + b0.y + bv.y);
            uint64_t acc1 = pack2(a1.x + b1.x + bv.z, a1.y + b1.y + bv.w);

            const float4* eap = (const float4*)(ea + (size_t)(base + j) * 16);
#pragma unroll
            for (int gq = 0; gq < 4; gq++) {
                float4 e4 = __ldg(&eap[gq]);   // uniform across warp -> broadcast
                uint64_t ex;
                ex = pack2(e4.x, e4.x);
                acc0 = fma2(wp0[gq * 4 + 0], ex, acc0);
                acc1 = fma2(wp1[gq * 4 + 0], ex, acc1);
                ex = pack2(e4.y, e4.y);
                acc0 = fma2(wp0[gq * 4 + 1], ex, acc0);
                acc1 = fma2(wp1[gq * 4 + 1], ex, acc1);
                ex = pack2(e4.z, e4.z);
                acc0 = fma2(wp0[gq * 4 + 2], ex, acc0);
                acc1 = fma2(wp1[gq * 4 + 2], ex, acc1);
                ex = pack2(e4.w, e4.w);
                acc0 = fma2(wp0[gq * 4 + 3], ex, acc0);
                acc1 = fma2(wp1[gq * 4 + 3], ex, acc1);
            }
            float f0, f1, f2, f3;
            unpack2(acc0, f0, f1);
            unpack2(acc1, f2, f3);
            f0 = fmaxf(f0, 0.f);
            f1 = fmaxf(f1, 0.f);
            f2 = fmaxf(f2, 0.f);
            f3 = fmaxf(f3, 0.f);

            float p = f0 * w2.x + f1 * w2.y + f2 * w2.z + f3 * w2.w;
#pragma unroll
            for (int o = 16; o; o >>= 1) p += __shfl_xor_sync(FULLMASK, p, o);
            if (lane == j) res = p + bm2v;
        }
        if (lane < m) out[base + lane] = res;   // coalesced 128B store
    }
}

// ---------------------------------------------------------------------------
extern "C" void kernel_launch(void* const* d_in, const int* in_sizes, int n_in,
                              void* d_out, int out_size)
{
    const float* x     = (const float*)d_in[0];
    const int*   ei    = (const int*)  d_in[1];
    const float* ea    = (const float*)d_in[2];
    const float* W1    = (const float*)d_in[3];
    const float* b1    = (const float*)d_in[4];
    const float* gamma = (const float*)d_in[5];
    const float* beta  = (const float*)d_in[6];
    const float* W2    = (const float*)d_in[7];
    const float* b2    = (const float*)d_in[8];
    const float* Wm1   = (const float*)d_in[9];
    const float* bm1   = (const float*)d_in[10];
    const float* Wm2   = (const float*)d_in[11];
    const float* bm2   = (const float*)d_in[12];
    float* out = (float*)d_out;

    const int Nn = in_sizes[0] / HID;
    const int E  = in_sizes[1] / 2;
    const int* src = ei;
    const int* dst = ei + E;

    float *buf0, *dinv, *sum, *sumsq, *scale, *shift;
    __half *h16, *A16, *B16;
    int *cnt, *rowoff, *cursor, *csr_src;
    cudaGetSymbolAddress((void**)&buf0,    g_buf0);
    cudaGetSymbolAddress((void**)&h16,     g_h16);
    cudaGetSymbolAddress((void**)&A16,     g_A16);
    cudaGetSymbolAddress((void**)&B16,     g_B16);
    cudaGetSymbolAddress((void**)&dinv,    g_dinv);
    cudaGetSymbolAddress((void**)&sum,     g_sum);
    cudaGetSymbolAddress((void**)&sumsq,   g_sumsq);
    cudaGetSymbolAddress((void**)&scale,   g_scale);
    cudaGetSymbolAddress((void**)&shift,   g_shift);
    cudaGetSymbolAddress((void**)&cnt,     g_cnt);
    cudaGetSymbolAddress((void**)&rowoff,  g_rowoff);
    cudaGetSymbolAddress((void**)&cursor,  g_cursor);
    cudaGetSymbolAddress((void**)&csr_src, g_csr_src);

    const int SMEM  = 2 * 128 * SMS * (int)sizeof(float);
    const int SMEMP = 128 * (SMS + WSS) * (int)sizeof(float);
    cudaFuncSetAttribute(gemm_tf32, cudaFuncAttributeMaxDynamicSharedMemorySize, SMEM);
    cudaFuncSetAttribute(gemm_proj, cudaFuncAttributeMaxDynamicSharedMemorySize, SMEMP);

    const int gN    = (Nn + 255) / 256;
    const int gE    = (E + 255) / 256;
    const int gGemm = (Nn + 127) / 128;
    const int gAgg  = (Nn * 32 + 255) / 256;

    // CSR build (by dst) + degrees
    zero_aux<<<gN, 256>>>(cnt, sum, sumsq, Nn);
    hist_dst<<<gE, 256>>>(dst, cnt, E);
    scan_offsets<<<1, 1024>>>(cnt, rowoff, cursor, dinv, Nn);
    fill_csr<<<gE, 256>>>(src, dst, cursor, csr_src, E);

    // conv1: h1 = x @ W1 (fp16) ; agg1 = CSR gather + self-loop + b1 (fp32)
    gemm_tf32<<<gGemm, 256, SMEM>>>(x, W1, h16, Nn, nullptr, nullptr);
    gcn_aggregate<<<gAgg, 256>>>(h16, buf0, rowoff, csr_src, dinv, b1, Nn);

    // batchnorm stats (apply fused into next GEMM's A staging)
    bn_stats<<<512, 256>>>(buf0, sum, sumsq, Nn);
    bn_final<<<1, 128>>>(sum, sumsq, gamma, beta, scale, shift, Nn);

    // conv2: h2 = relu(bn(agg1)) @ W2 (fp16) ; agg2 (fp32, reuse buf0)
    gemm_tf32<<<gGemm, 256, SMEM>>>(buf0, W2, h16, Nn, scale, shift);
    gcn_aggregate<<<gAgg, 256>>>(h16, buf0, rowoff, csr_src, dinv, b2, Nn);

    // fused per-node projections: A16 = z2@Wm1[0:128], B16 = z2@Wm1[128:256]
    gemm_proj<<<gGemm, 512, SMEMP>>>(buf0, Wm1, A16, B16, Nn);

    // fused edge head
    edge_mlp<<<2048, 256>>>(A16, B16, src, dst, ea, Wm1 + 256 * HID,
                            bm1, Wm2, bm2, out, E);
}